// round 11
// baseline (speedup 1.0000x reference)
#include <cuda_runtime.h>
#include <cuda_bf16.h>
#include <cuda_fp8.h>
#include <math.h>
#include <stdint.h>

#define N_TOK 65536
#define HDIM  1024
#define NEXP  3
#define NCH   32          // 8 fp8 (lo*hi) + 8 fp8 (hi*lo) + 16 bf16 (hi*hi)
#define BM    128
#define BN    64

typedef __nv_bfloat16 bf16;

// ------------------- scratch (allocation-free) -------------------
__device__ int     g_cursor[NEXP];
__device__ int     g_idx[NEXP * N_TOK];
__device__ bf16    g_xhi [(size_t)N_TOK * HDIM];
__device__ uint8_t g_xhi8[(size_t)N_TOK * HDIM];
__device__ uint8_t g_xlo8[(size_t)N_TOK * HDIM];   // e4m3(x_lo * 512)
__device__ bf16    g_ihi [(size_t)N_TOK * HDIM];
__device__ uint8_t g_ihi8[(size_t)N_TOK * HDIM];
__device__ uint8_t g_ilo8[(size_t)N_TOK * HDIM];   // e4m3(i_lo * 512)
__device__ bf16    g_w1hi [(size_t)NEXP * HDIM * HDIM];
__device__ uint8_t g_w1hi8[(size_t)NEXP * HDIM * HDIM];
__device__ uint8_t g_w1lo8[(size_t)NEXP * HDIM * HDIM];  // e4m3(w_lo*512)
__device__ bf16    g_w3hi [(size_t)NEXP * HDIM * HDIM];
__device__ uint8_t g_w3hi8[(size_t)NEXP * HDIM * HDIM];
__device__ uint8_t g_w3lo8[(size_t)NEXP * HDIM * HDIM];
__device__ bf16    g_w2hi [(size_t)NEXP * HDIM * HDIM];
__device__ uint8_t g_w2hi8[(size_t)NEXP * HDIM * HDIM];
__device__ uint8_t g_w2lo8[(size_t)NEXP * HDIM * HDIM];

// ------------------- helpers -------------------
__device__ __forceinline__ uint32_t s2u(const void* p) {
    return (uint32_t)__cvta_generic_to_shared(p);
}
__device__ __forceinline__ void cp16(uint32_t dst, const void* src) {
    asm volatile("cp.async.cg.shared.global [%0], [%1], 16;" :: "r"(dst), "l"(src));
}
#define CP_COMMIT() asm volatile("cp.async.commit_group;" ::: "memory")
#define CP_WAIT(n)  asm volatile("cp.async.wait_group %0;" :: "n"(n) : "memory")

#define LDSM4(r0,r1,r2,r3,addr) \
    asm volatile("ldmatrix.sync.aligned.m8n8.x4.shared.b16 {%0,%1,%2,%3}, [%4];" \
        : "=r"(r0), "=r"(r1), "=r"(r2), "=r"(r3) : "r"(addr))

#define MMA16816(d, a0,a1,a2,a3, b0,b1) \
    asm volatile("mma.sync.aligned.m16n8k16.row.col.f32.bf16.bf16.f32 " \
        "{%0,%1,%2,%3}, {%4,%5,%6,%7}, {%8,%9}, {%0,%1,%2,%3};" \
        : "+f"((d)[0]), "+f"((d)[1]), "+f"((d)[2]), "+f"((d)[3]) \
        : "r"(a0), "r"(a1), "r"(a2), "r"(a3), "r"(b0), "r"(b1))

#define MMAFP8(d, a0,a1,a2,a3, b0,b1) \
    asm volatile("mma.sync.aligned.m16n8k32.row.col.f32.e4m3.e4m3.f32 " \
        "{%0,%1,%2,%3}, {%4,%5,%6,%7}, {%8,%9}, {%0,%1,%2,%3};" \
        : "+f"((d)[0]), "+f"((d)[1]), "+f"((d)[2]), "+f"((d)[3]) \
        : "r"(a0), "r"(a1), "r"(a2), "r"(a3), "r"(b0), "r"(b1))

__device__ __forceinline__ uint32_t swz(uint32_t o) { return o ^ ((o >> 3) & 0x70); }

__device__ __forceinline__ float act_fn(float h1, int e) {
    if (e == 0) return h1 / (1.0f + __expf(-h1));
    if (e == 1) return 0.5f * h1 * (1.0f + erff(h1 * 0.70710678118654752f));
    return fmaxf(h1, 0.0f);
}
__device__ __forceinline__ uint32_t pack_bf2(float a, float b) {
    __nv_bfloat162 t = __halves2bfloat162(__float2bfloat16_rn(a), __float2bfloat16_rn(b));
    return *(uint32_t*)&t;
}
__device__ __forceinline__ uint8_t f2e4m3(float v) {
    return (uint8_t)__nv_cvt_float_to_fp8(v, __NV_SATFINITE, __NV_E4M3);
}

// ============================================================
// Kernel 0: zero per-expert cursors
// ============================================================
__global__ void zero_kernel() {
    if (threadIdx.x < NEXP) g_cursor[threadIdx.x] = 0;
}

// ============================================================
// Kernel 1: gating (one warp per token)
// ============================================================
__global__ void gate_kernel(const float* __restrict__ x,
                            const float* __restrict__ Wg,
                            const float* __restrict__ bg,
                            const float* __restrict__ gu) {
    __shared__ float sWg[HDIM * NEXP];
    int tid = threadIdx.x;
    for (int t = tid; t < HDIM * NEXP; t += blockDim.x) sWg[t] = Wg[t];
    __syncthreads();

    int warp = tid >> 5, lane = tid & 31;
    int n = blockIdx.x * 8 + warp;
    const float* xr = x + (size_t)n * HDIM;

    float a0 = 0.f, a1 = 0.f, a2 = 0.f;
    #pragma unroll 8
    for (int j = 0; j < HDIM; j += 32) {
        float xi = xr[j + lane];
        const float* w = &sWg[(j + lane) * 3];
        a0 += xi * w[0];
        a1 += xi * w[1];
        a2 += xi * w[2];
    }
    #pragma unroll
    for (int off = 16; off > 0; off >>= 1) {
        a0 += __shfl_down_sync(0xffffffffu, a0, off);
        a1 += __shfl_down_sync(0xffffffffu, a1, off);
        a2 += __shfl_down_sync(0xffffffffu, a2, off);
    }
    if (lane == 0) {
        float s[3];
        s[0] = a0 + bg[0];
        s[1] = a1 + bg[1];
        s[2] = a2 + bg[2];
        #pragma unroll
        for (int e = 0; e < 3; e++) {
            float u = gu[(size_t)n * 3 + e];
            u = fminf(fmaxf(u, 1e-6f), 1.0f - 1e-6f);
            s[e] += -logf(-logf(u));
        }
        int best = 0;
        if (s[1] > s[best]) best = 1;
        if (s[2] > s[best]) best = 2;
        int pos = atomicAdd(&g_cursor[best], 1);
        g_idx[best * N_TOK + pos] = n;
    }
}

// ============================================================
// Kernel 2: split x -> bf16 hi, e4m3(hi), e4m3(lo*512)
// ============================================================
__global__ void xsplit_kernel(const float* __restrict__ x) {
    size_t i = ((size_t)blockIdx.x * 256 + threadIdx.x) * 4;
    float4 v = *(const float4*)(x + i);
    float vv[4] = {v.x, v.y, v.z, v.w};
    bf16 h[4];
    uint32_t hi8 = 0, lo8 = 0;
    #pragma unroll
    for (int k = 0; k < 4; k++) {
        h[k] = __float2bfloat16_rn(vv[k]);
        float lo = vv[k] - __bfloat162float(h[k]);
        hi8 |= (uint32_t)f2e4m3(vv[k]) << (8 * k);
        lo8 |= (uint32_t)f2e4m3(lo * 512.0f) << (8 * k);
    }
    __nv_bfloat162 ha = __halves2bfloat162(h[0], h[1]), hb = __halves2bfloat162(h[2], h[3]);
    *(uint2*)(g_xhi + i) = make_uint2(*(uint32_t*)&ha, *(uint32_t*)&hb);
    *(uint32_t*)(g_xhi8 + i) = hi8;
    *(uint32_t*)(g_xlo8 + i) = lo8;
}

// ============================================================
// Kernel 3: transpose + split weights (K-major)
// ============================================================
__global__ void wsplit_kernel(const float* __restrict__ W1,
                              const float* __restrict__ W3,
                              const float* __restrict__ W2) {
    __shared__ float t[32][33];
    int z = blockIdx.z;
    int mat = z / 3, e = z % 3;
    const float* src;
    bf16* dh; uint8_t *dh8, *dl8;
    if (mat == 0)      { src = W1; dh = g_w1hi; dh8 = g_w1hi8; dl8 = g_w1lo8; }
    else if (mat == 1) { src = W3; dh = g_w3hi; dh8 = g_w3hi8; dl8 = g_w3lo8; }
    else               { src = W2; dh = g_w2hi; dh8 = g_w2hi8; dl8 = g_w2lo8; }
    size_t eo = (size_t)e * HDIM * HDIM;
    src += eo; dh += eo; dh8 += eo; dl8 += eo;

    int bx = blockIdx.x * 32, by = blockIdx.y * 32;
    int tx = threadIdx.x;
    for (int i = threadIdx.y; i < 32; i += 8)
        t[i][tx] = src[(size_t)(by + i) * HDIM + bx + tx];
    __syncthreads();
    for (int i = threadIdx.y; i < 32; i += 8) {
        float v = t[tx][i];                              // = W[by+tx][bx+i]
        size_t di = (size_t)(bx + i) * HDIM + by + tx;   // Wt[h][d]
        bf16 h = __float2bfloat16_rn(v);
        float lo = v - __bfloat162float(h);
        dh[di]  = h;
        dh8[di] = f2e4m3(v);
        dl8[di] = f2e4m3(lo * 512.0f);
    }
}

// ============================================================
// Kernel 4: pass A — fp8 cross terms + bf16 main, dual GEMM
//   Tile 128x64, 256 threads, 4m x 2n, 3-stage, 2 CTAs/SM.
//   Chunks 0-7:  e4m3(x_lo*512) . e4m3(w_hi)     [K=128/chunk]
//   Chunks 8-15: e4m3(x_hi)     . e4m3(w_lo*512) [K=128/chunk]
//   acc *= 1/512
//   Chunks 16-31: bf16 x_hi . w_hi               [K=64/chunk]
//   grid (16, 512, 3)
// ============================================================
#define A_STG  32768
#define A_NST  3
#define A_SMEM (2048 + A_NST * A_STG)

__global__ __launch_bounds__(256, 2)
void passA_mma(const float* __restrict__ b1, const float* __restrict__ b3) {
    int e    = blockIdx.z;
    int cnt  = g_cursor[e];
    int base = blockIdx.y * BM;
    if (base >= cnt) return;
    int n0  = blockIdx.x * BN;
    int tid = threadIdx.x, wid = tid >> 5, lane = tid & 31;
    int m32 = (wid & 3) * 32;
    int n32 = (wid >> 2) * 32;

    extern __shared__ char smem[];
    uint32_t sb = s2u(smem);

    int off = 0;
    for (int i = 0; i < e; i++) off += g_cursor[i];

    int*   srow = (int*)(smem);
    float* sb1  = (float*)(smem + 512);
    float* sb3  = (float*)(smem + 768);
    if (tid < BM) {
        int p = base + tid;
        srow[tid] = (p < cnt) ? g_idx[e * N_TOK + p] : g_idx[e * N_TOK];
    }
    if (tid < BN) {
        sb1[tid] = b1[e * HDIM + n0 + tid];
        sb3[tid] = b3[e * HDIM + n0 + tid];
    }
    __syncthreads();

    size_t eo = (size_t)e * HDIM * HDIM;
    const bf16*    w1h  = g_w1hi  + eo;
    const bf16*    w3h  = g_w3hi  + eo;
    const uint8_t* w1h8 = g_w1hi8 + eo;
    const uint8_t* w3h8 = g_w3hi8 + eo;
    const uint8_t* w1l8 = g_w1lo8 + eo;
    const uint8_t* w3l8 = g_w3lo8 + eo;

    // hoisted gather addressing
    int rr   = tid >> 3;
    int ce   = (tid & 7) * 8;             // elem col (bf16)
    int cb   = (tid & 7) * 16;            // byte col (fp8)
    uint32_t asw = swz((uint32_t)((rr << 7) | ((tid & 7) << 4)));
    size_t arow[4];
    #pragma unroll
    for (int it = 0; it < 4; it++)
        arow[it] = (size_t)srow[rr + 32 * it] * HDIM;
    size_t brow = (size_t)(n0 + rr) * HDIM;

    auto load_chunk = [&](int c) {
        int st = c % A_NST;
        uint32_t sa = sb + 2048 + st * A_STG;
        if (c < 16) {
            int kb = (c & 7) * 128;       // byte col base, K=128 fp8
            const uint8_t* A8  = (c < 8) ? g_xlo8 : g_xhi8;
            const uint8_t* B18 = (c < 8) ? w1h8 : w1l8;
            const uint8_t* B38 = (c < 8) ? w3h8 : w3l8;
            #pragma unroll
            for (int it = 0; it < 4; it++)
                cp16(sa + asw + it * 4096, A8 + arow[it] + kb + cb);
            #pragma unroll
            for (int it = 0; it < 2; it++) {
                size_t g = brow + (size_t)(it * 32) * HDIM + kb + cb;
                cp16(sa + 16384 + asw + it * 4096, B18 + g);
                cp16(sa + 24576 + asw + it * 4096, B38 + g);
            }
        } else {
            int kk0 = ((c - 16) & 15) << 6;   // elem col base, K=64 bf16
            #pragma unroll
            for (int it = 0; it < 4; it++)
                cp16(sa + asw + it * 4096, g_xhi + arow[it] + kk0 + ce);
            #pragma unroll
            for (int it = 0; it < 2; it++) {
                size_t g = brow + (size_t)(it * 32) * HDIM + kk0 + ce;
                cp16(sa + 16384 + asw + it * 4096, w1h + g);
                cp16(sa + 24576 + asw + it * 4096, w3h + g);
            }
        }
        CP_COMMIT();
    };

    int arow_lm = (lane & 15);
    int ahalf   = (lane >> 4);
    int nrow_lm = ((lane >> 4) << 3) + (lane & 7);
    int bhalf   = (lane >> 3) & 1;

    float acc1[2][4][4];
    float acc3[2][4][4];
    #pragma unroll
    for (int i = 0; i < 2; i++)
        #pragma unroll
        for (int j = 0; j < 4; j++)
            #pragma unroll
            for (int q = 0; q < 4; q++) { acc1[i][j][q] = 0.f; acc3[i][j][q] = 0.f; }

    load_chunk(0); load_chunk(1);

    for (int c = 0; c < NCH; c++) {
        CP_WAIT(1);
        __syncthreads();
        if (c + 2 < NCH) load_chunk(c + 2);
        else CP_COMMIT();
        if (c == 16) {      // cross terms done -> scale by 1/512
            #pragma unroll
            for (int i = 0; i < 2; i++)
                #pragma unroll
                for (int j = 0; j < 4; j++)
                    #pragma unroll
                    for (int q = 0; q < 4; q++) {
                        acc1[i][j][q] *= 0.001953125f;
                        acc3[i][j][q] *= 0.001953125f;
                    }
        }
        uint32_t sa = sb + 2048 + (c % A_NST) * A_STG;
        bool f8 = (c < 16);
        #pragma unroll
        for (int kk = 0; kk < 4; kk++) {
            uint32_t a[2][4];
            #pragma unroll
            for (int i = 0; i < 2; i++) {
                int row = m32 + i * 16 + arow_lm;
                uint32_t o = (uint32_t)(row * 128 + (kk * 2 + ahalf) * 16);
                LDSM4(a[i][0], a[i][1], a[i][2], a[i][3], sa + swz(o));
            }
            #pragma unroll
            for (int jj = 0; jj < 2; jj++) {
                int nrow = n32 + jj * 16 + nrow_lm;
                uint32_t sw = swz((uint32_t)(nrow * 128 + (kk * 2 + bhalf) * 16));
                uint32_t b0, b1r, b2r, b3r, c0, c1r, c2r, c3r;
                LDSM4(b0, b1r, b2r, b3r, sa + 16384 + sw);
                LDSM4(c0, c1r, c2r, c3r, sa + 24576 + sw);
                if (f8) {
                    #pragma unroll
                    for (int i = 0; i < 2; i++) {
                        MMAFP8(acc1[i][2*jj],   a[i][0], a[i][1], a[i][2], a[i][3], b0, b1r);
                        MMAFP8(acc1[i][2*jj+1], a[i][0], a[i][1], a[i][2], a[i][3], b2r, b3r);
                        MMAFP8(acc3[i][2*jj],   a[i][0], a[i][1], a[i][2], a[i][3], c0, c1r);
                        MMAFP8(acc3[i][2*jj+1], a[i][0], a[i][1], a[i][2], a[i][3], c2r, c3r);
                    }
                } else {
                    #pragma unroll
                    for (int i = 0; i < 2; i++) {
                        MMA16816(acc1[i][2*jj],   a[i][0], a[i][1], a[i][2], a[i][3], b0, b1r);
                        MMA16816(acc1[i][2*jj+1], a[i][0], a[i][1], a[i][2], a[i][3], b2r, b3r);
                        MMA16816(acc3[i][2*jj],   a[i][0], a[i][1], a[i][2], a[i][3], c0, c1r);
                        MMA16816(acc3[i][2*jj+1], a[i][0], a[i][1], a[i][2], a[i][3], c2r, c3r);
                    }
                }
            }
        }
    }

    // epilogue: bias + activation; store inner as bf16-hi + fp8(hi) + fp8(lo*512)
    int mrows = cnt - base; if (mrows > BM) mrows = BM;
    #pragma unroll
    for (int i = 0; i < 2; i++) {
        int r0 = m32 + i * 16 + (lane >> 2);
        int r1 = r0 + 8;
        size_t g0 = (size_t)(off + base + r0) * HDIM;
        size_t g1 = (size_t)(off + base + r1) * HDIM;
        #pragma unroll
        for (int j = 0; j < 4; j++) {
            int n = n32 + j * 8 + (lane & 3) * 2;
            float bb1a = sb1[n], bb1b = sb1[n + 1];
            float bb3a = sb3[n], bb3b = sb3[n + 1];
            if (r0 < mrows) {
                float v0 = act_fn(acc1[i][j][0] + bb1a, e) * (acc3[i][j][0] + bb3a);
                float v1 = act_fn(acc1[i][j][1] + bb1b, e) * (acc3[i][j][1] + bb3b);
                bf16 h0 = __float2bfloat16_rn(v0), h1 = __float2bfloat16_rn(v1);
                *(uint32_t*)(g_ihi + g0 + n0 + n) = pack_bf2(v0, v1);
                *(uint16_t*)(g_ihi8 + g0 + n0 + n) =
                    (uint16_t)(f2e4m3(v0) | ((uint16_t)f2e4m3(v1) << 8));
                float l0 = (v0 - __bfloat162float(h0)) * 512.0f;
                float l1 = (v1 - __bfloat162float(h1)) * 512.0f;
                *(uint16_t*)(g_ilo8 + g0 + n0 + n) =
                    (uint16_t)(f2e4m3(l0) | ((uint16_t)f2e4m3(l1) << 8));
            }
            if (r1 < mrows) {
                float v2 = act_fn(acc1[i][j][2] + bb1a, e) * (acc3[i][j][2] + bb3a);
                float v3 = act_fn(acc1[i][j][3] + bb1b, e) * (acc3[i][j][3] + bb3b);
                bf16 h2 = __float2bfloat16_rn(v2), h3 = __float2bfloat16_rn(v3);
                *(uint32_t*)(g_ihi + g1 + n0 + n) = pack_bf2(v2, v3);
                *(uint16_t*)(g_ihi8 + g1 + n0 + n) =
                    (uint16_t)(f2e4m3(v2) | ((uint16_t)f2e4m3(v3) << 8));
                float l2 = (v2 - __bfloat162float(h2)) * 512.0f;
                float l3 = (v3 - __bfloat162float(h3)) * 512.0f;
                *(uint16_t*)(g_ilo8 + g1 + n0 + n) =
                    (uint16_t)(f2e4m3(l2) | ((uint16_t)f2e4m3(l3) << 8));
            }
        }
    }
}

// ============================================================
// Kernel 5: pass B — fp8 cross + bf16 main, inner@W2 + b2, scatter
//   Tile 128x64, 256 threads, 3-stage. grid (16, 512, 3)
// ============================================================
#define B_STG  24576
#define B_NST  3
#define B_SMEM (2048 + B_NST * B_STG)

__global__ __launch_bounds__(256, 2)
void passB_mma(const float* __restrict__ b2, float* __restrict__ out) {
    int e    = blockIdx.z;
    int cnt  = g_cursor[e];
    int base = blockIdx.y * BM;
    if (base >= cnt) return;
    int n0  = blockIdx.x * BN;
    int tid = threadIdx.x, wid = tid >> 5, lane = tid & 31;
    int m32 = (wid & 3) * 32;
    int n32 = (wid >> 2) * 32;

    extern __shared__ char smem[];
    uint32_t sb = s2u(smem);

    int off = 0;
    for (int i = 0; i < e; i++) off += g_cursor[i];

    int*   stok = (int*)(smem);
    float* sb2  = (float*)(smem + 512);
    if (tid < BM) {
        int p = base + tid;
        stok[tid] = (p < cnt) ? g_idx[e * N_TOK + p] : 0;
    }
    if (tid < BN) sb2[tid] = b2[e * HDIM + n0 + tid];
    __syncthreads();

    size_t eo = (size_t)e * HDIM * HDIM;
    const bf16*    w2h  = g_w2hi  + eo;
    const uint8_t* w2h8 = g_w2hi8 + eo;
    const uint8_t* w2l8 = g_w2lo8 + eo;

    int rr   = tid >> 3;
    int ce   = (tid & 7) * 8;
    int cb   = (tid & 7) * 16;
    uint32_t asw = swz((uint32_t)((rr << 7) | ((tid & 7) << 4)));
    size_t arow[4];
    #pragma unroll
    for (int it = 0; it < 4; it++) {
        int row  = rr + 32 * it;
        int ar   = (base + row < cnt) ? (off + base + row) : off;
        arow[it] = (size_t)ar * HDIM;
    }
    size_t brow = (size_t)(n0 + rr) * HDIM;

    auto load_chunk = [&](int c) {
        int st = c % B_NST;
        uint32_t sa = sb + 2048 + st * B_STG;
        if (c < 16) {
            int kb = (c & 7) * 128;
            const uint8_t* A8 = (c < 8) ? g_ilo8 : g_ihi8;
            const uint8_t* B8 = (c < 8) ? w2h8 : w2l8;
            #pragma unroll
            for (int it = 0; it < 4; it++)
                cp16(sa + asw + it * 4096, A8 + arow[it] + kb + cb);
            #pragma unroll
            for (int it = 0; it < 2; it++)
                cp16(sa + 16384 + asw + it * 4096,
                     B8 + brow + (size_t)(it * 32) * HDIM + kb + cb);
        } else {
            int kk0 = ((c - 16) & 15) << 6;
            #pragma unroll
            for (int it = 0; it < 4; it++)
                cp16(sa + asw + it * 4096, g_ihi + arow[it] + kk0 + ce);
            #pragma unroll
            for (int it = 0; it < 2; it++)
                cp16(sa + 16384 + asw + it * 4096,
                     w2h + brow + (size_t)(it * 32) * HDIM + kk0 + ce);
        }
        CP_COMMIT();
    };

    int arow_lm = (lane & 15);
    int ahalf   = (lane >> 4);
    int nrow_lm = ((lane >> 4) << 3) + (lane & 7);
    int bhalf   = (lane >> 3) & 1;

    float acc[2][4][4];
    #pragma unroll
    for (int i = 0; i < 2; i++)
        #pragma unroll
        for (int j = 0; j < 4; j++)
            #pragma unroll
            for (int q = 0; q < 4; q++) acc[i][j][q] = 0.f;

    load_chunk(0); load_chunk(1);

    for (int c = 0; c < NCH; c++) {
        CP_WAIT(1);
        __syncthreads();
        if (c + 2 < NCH) load_chunk(c + 2);
        else CP_COMMIT();
        if (c == 16) {
            #pragma unroll
            for (int i = 0; i < 2; i++)
                #pragma unroll
                for (int j = 0; j < 4; j++)
                    #pragma unroll
                    for (int q = 0; q < 4; q++) acc[i][j][q] *= 0.001953125f;
        }
        uint32_t sa = sb + 2048 + (c % B_NST) * B_STG;
        bool f8 = (c < 16);
        #pragma unroll
        for (int kk = 0; kk < 4; kk++) {
            uint32_t a[2][4];
            #pragma unroll
            for (int i = 0; i < 2; i++) {
                int row = m32 + i * 16 + arow_lm;
                uint32_t o = (uint32_t)(row * 128 + (kk * 2 + ahalf) * 16);
                LDSM4(a[i][0], a[i][1], a[i][2], a[i][3], sa + swz(o));
            }
            #pragma unroll
            for (int jj = 0; jj < 2; jj++) {
                int nrow = n32 + jj * 16 + nrow_lm;
                uint32_t sw = swz((uint32_t)(nrow * 128 + (kk * 2 + bhalf) * 16));
                uint32_t b0, b1r, b2r, b3r;
                LDSM4(b0, b1r, b2r, b3r, sa + 16384 + sw);
                if (f8) {
                    #pragma unroll
                    for (int i = 0; i < 2; i++) {
                        MMAFP8(acc[i][2*jj],   a[i][0], a[i][1], a[i][2], a[i][3], b0, b1r);
                        MMAFP8(acc[i][2*jj+1], a[i][0], a[i][1], a[i][2], a[i][3], b2r, b3r);
                    }
                } else {
                    #pragma unroll
                    for (int i = 0; i < 2; i++) {
                        MMA16816(acc[i][2*jj],   a[i][0], a[i][1], a[i][2], a[i][3], b0, b1r);
                        MMA16816(acc[i][2*jj+1], a[i][0], a[i][1], a[i][2], a[i][3], b2r, b3r);
                    }
                }
            }
        }
    }

    int mrows = cnt - base; if (mrows > BM) mrows = BM;
    #pragma unroll
    for (int i = 0; i < 2; i++) {
        int r0 = m32 + i * 16 + (lane >> 2);
        int r1 = r0 + 8;
        float* d0 = out + (size_t)stok[r0] * HDIM + n0;
        float* d1 = out + (size_t)stok[r1 < BM ? r1 : 0] * HDIM + n0;
        #pragma unroll
        for (int j = 0; j < 4; j++) {
            int n = n32 + j * 8 + (lane & 3) * 2;
            float ba = sb2[n], bb = sb2[n + 1];
            if (r0 < mrows) {
                float2 o0 = make_float2(acc[i][j][0] + ba, acc[i][j][1] + bb);
                *(float2*)(d0 + n) = o0;
            }
            if (r1 < mrows) {
                float2 o1 = make_float2(acc[i][j][2] + ba, acc[i][j][3] + bb);
                *(float2*)(d1 + n) = o1;
            }
        }
    }
}

// ============================================================
extern "C" void kernel_launch(void* const* d_in, const int* in_sizes, int n_in,
                              void* d_out, int out_size) {
    (void)in_sizes; (void)n_in; (void)out_size;
    const float* x  = (const float*)d_in[0];
    const float* W1 = (const float*)d_in[1];
    const float* b1 = (const float*)d_in[2];
    const float* W2 = (const float*)d_in[3];
    const float* b2 = (const float*)d_in[4];
    const float* W3 = (const float*)d_in[5];
    const float* b3 = (const float*)d_in[6];
    const float* Wg = (const float*)d_in[7];
    const float* bg = (const float*)d_in[8];
    const float* gu = (const float*)d_in[9];
    float* out = (float*)d_out;

    cudaFuncSetAttribute(passA_mma, cudaFuncAttributeMaxDynamicSharedMemorySize, A_SMEM);
    cudaFuncSetAttribute(passB_mma, cudaFuncAttributeMaxDynamicSharedMemorySize, B_SMEM);

    zero_kernel<<<1, 32>>>();
    gate_kernel<<<N_TOK / 8, 256>>>(x, Wg, bg, gu);
    xsplit_kernel<<<(int)(((size_t)N_TOK * HDIM) / 1024), 256>>>(x);
    {
        dim3 g(32, 32, 9), b(32, 8);
        wsplit_kernel<<<g, b>>>(W1, W3, W2);
    }
    {
        dim3 grid(HDIM / BN, N_TOK / BM, NEXP);
        passA_mma<<<grid, 256, A_SMEM>>>(b1, b3);
        passB_mma<<<grid, 256, B_SMEM>>>(b2, out);
    }
}

// round 12
// speedup vs baseline: 1.6284x; 1.6284x over previous
#include <cuda_runtime.h>
#include <cuda_bf16.h>
#include <math.h>
#include <stdint.h>

#define N_TOK 65536
#define HDIM  1024
#define NEXP  3
#define NCH   32          // 16 chunks P = hi.hi  +  16 chunks Q = u.v
#define BM    128
#define BN    64
#define EPS   0.03125f    // 2^-5
#define OMEPS 0.96875f    // 1 - 2^-5

typedef __nv_bfloat16 bf16;

// ------------------- scratch (allocation-free) -------------------
__device__ int  g_cursor[NEXP];
__device__ int  g_idx[NEXP * N_TOK];
__device__ bf16 g_xhi[(size_t)N_TOK * HDIM];
__device__ bf16 g_xu [(size_t)N_TOK * HDIM];   // bf16(x_lo + EPS*x_hi)
__device__ bf16 g_ihi[(size_t)N_TOK * HDIM];
__device__ bf16 g_iu [(size_t)N_TOK * HDIM];
__device__ bf16 g_w1hi[(size_t)NEXP * HDIM * HDIM];
__device__ bf16 g_w1v [(size_t)NEXP * HDIM * HDIM];  // bf16(w_hi + w_lo/EPS)
__device__ bf16 g_w3hi[(size_t)NEXP * HDIM * HDIM];
__device__ bf16 g_w3v [(size_t)NEXP * HDIM * HDIM];
__device__ bf16 g_w2hi[(size_t)NEXP * HDIM * HDIM];
__device__ bf16 g_w2v [(size_t)NEXP * HDIM * HDIM];

// ------------------- helpers -------------------
__device__ __forceinline__ uint32_t s2u(const void* p) {
    return (uint32_t)__cvta_generic_to_shared(p);
}
__device__ __forceinline__ void cp16(uint32_t dst, const void* src) {
    asm volatile("cp.async.cg.shared.global [%0], [%1], 16;" :: "r"(dst), "l"(src));
}
#define CP_COMMIT() asm volatile("cp.async.commit_group;" ::: "memory")
#define CP_WAIT(n)  asm volatile("cp.async.wait_group %0;" :: "n"(n) : "memory")

#define LDSM4(r0,r1,r2,r3,addr) \
    asm volatile("ldmatrix.sync.aligned.m8n8.x4.shared.b16 {%0,%1,%2,%3}, [%4];" \
        : "=r"(r0), "=r"(r1), "=r"(r2), "=r"(r3) : "r"(addr))

#define MMA16816(d, a0,a1,a2,a3, b0,b1) \
    asm volatile("mma.sync.aligned.m16n8k16.row.col.f32.bf16.bf16.f32 " \
        "{%0,%1,%2,%3}, {%4,%5,%6,%7}, {%8,%9}, {%0,%1,%2,%3};" \
        : "+f"((d)[0]), "+f"((d)[1]), "+f"((d)[2]), "+f"((d)[3]) \
        : "r"(a0), "r"(a1), "r"(a2), "r"(a3), "r"(b0), "r"(b1))

__device__ __forceinline__ uint32_t swz(uint32_t o) { return o ^ ((o >> 3) & 0x70); }

__device__ __forceinline__ float act_fn(float h1, int e) {
    if (e == 0) return h1 / (1.0f + __expf(-h1));
    if (e == 1) return 0.5f * h1 * (1.0f + erff(h1 * 0.70710678118654752f));
    return fmaxf(h1, 0.0f);
}
__device__ __forceinline__ uint32_t pack_bf2(float a, float b) {
    __nv_bfloat162 t = __halves2bfloat162(__float2bfloat16_rn(a), __float2bfloat16_rn(b));
    return *(uint32_t*)&t;
}

// ============================================================
// Kernel 0: zero per-expert cursors
// ============================================================
__global__ void zero_kernel() {
    if (threadIdx.x < NEXP) g_cursor[threadIdx.x] = 0;
}

// ============================================================
// Kernel 1: gating (one warp per token)
// ============================================================
__global__ void gate_kernel(const float* __restrict__ x,
                            const float* __restrict__ Wg,
                            const float* __restrict__ bg,
                            const float* __restrict__ gu) {
    __shared__ float sWg[HDIM * NEXP];
    int tid = threadIdx.x;
    for (int t = tid; t < HDIM * NEXP; t += blockDim.x) sWg[t] = Wg[t];
    __syncthreads();

    int warp = tid >> 5, lane = tid & 31;
    int n = blockIdx.x * 8 + warp;
    const float* xr = x + (size_t)n * HDIM;

    float a0 = 0.f, a1 = 0.f, a2 = 0.f;
    #pragma unroll 8
    for (int j = 0; j < HDIM; j += 32) {
        float xi = xr[j + lane];
        const float* w = &sWg[(j + lane) * 3];
        a0 += xi * w[0];
        a1 += xi * w[1];
        a2 += xi * w[2];
    }
    #pragma unroll
    for (int off = 16; off > 0; off >>= 1) {
        a0 += __shfl_down_sync(0xffffffffu, a0, off);
        a1 += __shfl_down_sync(0xffffffffu, a1, off);
        a2 += __shfl_down_sync(0xffffffffu, a2, off);
    }
    if (lane == 0) {
        float s[3];
        s[0] = a0 + bg[0];
        s[1] = a1 + bg[1];
        s[2] = a2 + bg[2];
        #pragma unroll
        for (int e = 0; e < 3; e++) {
            float u = gu[(size_t)n * 3 + e];
            u = fminf(fmaxf(u, 1e-6f), 1.0f - 1e-6f);
            s[e] += -logf(-logf(u));
        }
        int best = 0;
        if (s[1] > s[best]) best = 1;
        if (s[2] > s[best]) best = 2;
        int pos = atomicAdd(&g_cursor[best], 1);
        g_idx[best * N_TOK + pos] = n;
    }
}

// ============================================================
// Kernel 2: split x -> bf16 hi  and  u = bf16(lo + EPS*hi)
// ============================================================
__global__ void xsplit_kernel(const float* __restrict__ x) {
    size_t i = ((size_t)blockIdx.x * 256 + threadIdx.x) * 4;
    float4 v = *(const float4*)(x + i);
    float vv[4] = {v.x, v.y, v.z, v.w};
    bf16 h[4], u[4];
    #pragma unroll
    for (int k = 0; k < 4; k++) {
        h[k] = __float2bfloat16_rn(vv[k]);
        float hf = __bfloat162float(h[k]);
        u[k] = __float2bfloat16_rn((vv[k] - hf) + EPS * hf);
    }
    __nv_bfloat162 ha = __halves2bfloat162(h[0], h[1]), hb = __halves2bfloat162(h[2], h[3]);
    __nv_bfloat162 ua = __halves2bfloat162(u[0], u[1]), ub = __halves2bfloat162(u[2], u[3]);
    *(uint2*)(g_xhi + i) = make_uint2(*(uint32_t*)&ha, *(uint32_t*)&hb);
    *(uint2*)(g_xu  + i) = make_uint2(*(uint32_t*)&ua, *(uint32_t*)&ub);
}

// ============================================================
// Kernel 3: transpose + split weights (K-major):
//   hi = bf16(w) ; v = bf16(hi + (w - hi)/EPS)
// ============================================================
__global__ void wsplit_kernel(const float* __restrict__ W1,
                              const float* __restrict__ W3,
                              const float* __restrict__ W2) {
    __shared__ float t[32][33];
    int z = blockIdx.z;
    int mat = z / 3, e = z % 3;
    const float* src;
    bf16 *dh, *dv;
    if (mat == 0)      { src = W1; dh = g_w1hi; dv = g_w1v; }
    else if (mat == 1) { src = W3; dh = g_w3hi; dv = g_w3v; }
    else               { src = W2; dh = g_w2hi; dv = g_w2v; }
    size_t eo = (size_t)e * HDIM * HDIM;
    src += eo; dh += eo; dv += eo;

    int bx = blockIdx.x * 32, by = blockIdx.y * 32;
    int tx = threadIdx.x;
    for (int i = threadIdx.y; i < 32; i += 8)
        t[i][tx] = src[(size_t)(by + i) * HDIM + bx + tx];
    __syncthreads();
    for (int i = threadIdx.y; i < 32; i += 8) {
        float w = t[tx][i];                              // = W[by+tx][bx+i]
        size_t di = (size_t)(bx + i) * HDIM + by + tx;   // Wt[h][d]
        bf16 h = __float2bfloat16_rn(w);
        float hf = __bfloat162float(h);
        dh[di] = h;
        dv[di] = __float2bfloat16_rn(hf + (w - hf) * (1.0f / EPS));
    }
}

// ============================================================
// Kernel 4: pass A — dual GEMM (h1, h3) + activation
//   result = (1-EPS)*P + Q ; P = hi.hi (chunks 0-15),
//   Q = u.v (chunks 16-31). Tile 128x64, 256 thr, 4m x 2n,
//   3-stage cp.async, 2 CTAs/SM. grid (16, 512, 3)
// ============================================================
#define A_STG  32768
#define A_NST  3
#define A_SMEM (2048 + A_NST * A_STG)

__global__ __launch_bounds__(256, 2)
void passA_mma(const float* __restrict__ b1, const float* __restrict__ b3) {
    int e    = blockIdx.z;
    int cnt  = g_cursor[e];
    int base = blockIdx.y * BM;
    if (base >= cnt) return;
    int n0  = blockIdx.x * BN;
    int tid = threadIdx.x, wid = tid >> 5, lane = tid & 31;
    int m32 = (wid & 3) * 32;
    int n32 = (wid >> 2) * 32;

    extern __shared__ char smem[];
    uint32_t sb = s2u(smem);

    int off = 0;
    for (int i = 0; i < e; i++) off += g_cursor[i];

    int*   srow = (int*)(smem);
    float* sb1  = (float*)(smem + 512);
    float* sb3  = (float*)(smem + 768);
    if (tid < BM) {
        int p = base + tid;
        srow[tid] = (p < cnt) ? g_idx[e * N_TOK + p] : g_idx[e * N_TOK];
    }
    if (tid < BN) {
        sb1[tid] = b1[e * HDIM + n0 + tid];
        sb3[tid] = b3[e * HDIM + n0 + tid];
    }
    __syncthreads();

    size_t eo = (size_t)e * HDIM * HDIM;
    const bf16* w1h = g_w1hi + eo;
    const bf16* w1v = g_w1v  + eo;
    const bf16* w3h = g_w3hi + eo;
    const bf16* w3v = g_w3v  + eo;

    // hoisted gather addressing
    int rr   = tid >> 3;
    int cseg = (tid & 7) * 8;
    uint32_t asw = swz((uint32_t)((rr << 7) | ((tid & 7) << 4)));
    size_t arow[4];
    #pragma unroll
    for (int it = 0; it < 4; it++)
        arow[it] = (size_t)srow[rr + 32 * it] * HDIM;
    size_t brow = (size_t)(n0 + rr) * HDIM;

    auto load_chunk = [&](int c) {
        int st  = c % A_NST;
        int kk0 = (c & 15) << 6;
        const bf16* As  = (c < 16) ? g_xhi : g_xu;
        const bf16* B1s = (c < 16) ? w1h : w1v;
        const bf16* B3s = (c < 16) ? w3h : w3v;
        uint32_t sa = sb + 2048 + st * A_STG;
        #pragma unroll
        for (int it = 0; it < 4; it++)
            cp16(sa + asw + it * 4096, As + arow[it] + kk0 + cseg);
        #pragma unroll
        for (int it = 0; it < 2; it++) {
            size_t g = brow + (size_t)(it * 32) * HDIM + kk0 + cseg;
            cp16(sa + 16384 + asw + it * 4096, B1s + g);
            cp16(sa + 24576 + asw + it * 4096, B3s + g);
        }
        CP_COMMIT();
    };

    int arow_lm = (lane & 15);
    int ahalf   = (lane >> 4);
    int nrow_lm = ((lane >> 4) << 3) + (lane & 7);
    int bhalf   = (lane >> 3) & 1;

    float acc1[2][4][4];
    float acc3[2][4][4];
    #pragma unroll
    for (int i = 0; i < 2; i++)
        #pragma unroll
        for (int j = 0; j < 4; j++)
            #pragma unroll
            for (int q = 0; q < 4; q++) { acc1[i][j][q] = 0.f; acc3[i][j][q] = 0.f; }

    load_chunk(0); load_chunk(1);

    for (int c = 0; c < NCH; c++) {
        CP_WAIT(1);
        __syncthreads();
        if (c + 2 < NCH) load_chunk(c + 2);
        else CP_COMMIT();                 // keep group count invariant for CP_WAIT(1)
        if (c == 16) {                    // P done -> scale by (1-EPS), then add Q
            #pragma unroll
            for (int i = 0; i < 2; i++)
                #pragma unroll
                for (int j = 0; j < 4; j++)
                    #pragma unroll
                    for (int q = 0; q < 4; q++) {
                        acc1[i][j][q] *= OMEPS;
                        acc3[i][j][q] *= OMEPS;
                    }
        }
        uint32_t sa = sb + 2048 + (c % A_NST) * A_STG;
        #pragma unroll
        for (int kk = 0; kk < 4; kk++) {
            uint32_t a[2][4];
            #pragma unroll
            for (int i = 0; i < 2; i++) {
                int row = m32 + i * 16 + arow_lm;
                uint32_t o = (uint32_t)(row * 128 + (kk * 2 + ahalf) * 16);
                LDSM4(a[i][0], a[i][1], a[i][2], a[i][3], sa + swz(o));
            }
            #pragma unroll
            for (int jj = 0; jj < 2; jj++) {
                int nrow = n32 + jj * 16 + nrow_lm;
                uint32_t sw = swz((uint32_t)(nrow * 128 + (kk * 2 + bhalf) * 16));
                uint32_t b0, b1r, b2r, b3r, c0, c1r, c2r, c3r;
                LDSM4(b0, b1r, b2r, b3r, sa + 16384 + sw);
                LDSM4(c0, c1r, c2r, c3r, sa + 24576 + sw);
                #pragma unroll
                for (int i = 0; i < 2; i++) {
                    MMA16816(acc1[i][2*jj],   a[i][0], a[i][1], a[i][2], a[i][3], b0, b1r);
                    MMA16816(acc1[i][2*jj+1], a[i][0], a[i][1], a[i][2], a[i][3], b2r, b3r);
                    MMA16816(acc3[i][2*jj],   a[i][0], a[i][1], a[i][2], a[i][3], c0, c1r);
                    MMA16816(acc3[i][2*jj+1], a[i][0], a[i][1], a[i][2], a[i][3], c2r, c3r);
                }
            }
        }
    }

    // epilogue: bias + activation; store inner as hi + u
    int mrows = cnt - base; if (mrows > BM) mrows = BM;
    #pragma unroll
    for (int i = 0; i < 2; i++) {
        int r0 = m32 + i * 16 + (lane >> 2);
        int r1 = r0 + 8;
        size_t g0 = (size_t)(off + base + r0) * HDIM;
        size_t g1 = (size_t)(off + base + r1) * HDIM;
        #pragma unroll
        for (int j = 0; j < 4; j++) {
            int n = n32 + j * 8 + (lane & 3) * 2;
            float bb1a = sb1[n], bb1b = sb1[n + 1];
            float bb3a = sb3[n], bb3b = sb3[n + 1];
            if (r0 < mrows) {
                float v0 = act_fn(acc1[i][j][0] + bb1a, e) * (acc3[i][j][0] + bb3a);
                float v1 = act_fn(acc1[i][j][1] + bb1b, e) * (acc3[i][j][1] + bb3b);
                bf16 h0 = __float2bfloat16_rn(v0), h1 = __float2bfloat16_rn(v1);
                float f0 = __bfloat162float(h0), f1 = __bfloat162float(h1);
                *(uint32_t*)(g_ihi + g0 + n0 + n) = pack_bf2(v0, v1);
                *(uint32_t*)(g_iu  + g0 + n0 + n) =
                    pack_bf2((v0 - f0) + EPS * f0, (v1 - f1) + EPS * f1);
            }
            if (r1 < mrows) {
                float v2 = act_fn(acc1[i][j][2] + bb1a, e) * (acc3[i][j][2] + bb3a);
                float v3 = act_fn(acc1[i][j][3] + bb1b, e) * (acc3[i][j][3] + bb3b);
                bf16 h2 = __float2bfloat16_rn(v2), h3 = __float2bfloat16_rn(v3);
                float f2 = __bfloat162float(h2), f3 = __bfloat162float(h3);
                *(uint32_t*)(g_ihi + g1 + n0 + n) = pack_bf2(v2, v3);
                *(uint32_t*)(g_iu  + g1 + n0 + n) =
                    pack_bf2((v2 - f2) + EPS * f2, (v3 - f3) + EPS * f3);
            }
        }
    }
}

// ============================================================
// Kernel 5: pass B — GEMM inner@W2 + b2, scatter
//   same (1-EPS)*P + Q scheme. grid (16, 512, 3)
// ============================================================
#define B_STG  24576
#define B_NST  3
#define B_SMEM (2048 + B_NST * B_STG)

__global__ __launch_bounds__(256, 2)
void passB_mma(const float* __restrict__ b2, float* __restrict__ out) {
    int e    = blockIdx.z;
    int cnt  = g_cursor[e];
    int base = blockIdx.y * BM;
    if (base >= cnt) return;
    int n0  = blockIdx.x * BN;
    int tid = threadIdx.x, wid = tid >> 5, lane = tid & 31;
    int m32 = (wid & 3) * 32;
    int n32 = (wid >> 2) * 32;

    extern __shared__ char smem[];
    uint32_t sb = s2u(smem);

    int off = 0;
    for (int i = 0; i < e; i++) off += g_cursor[i];

    int*   stok = (int*)(smem);
    float* sb2  = (float*)(smem + 512);
    if (tid < BM) {
        int p = base + tid;
        stok[tid] = (p < cnt) ? g_idx[e * N_TOK + p] : 0;
    }
    if (tid < BN) sb2[tid] = b2[e * HDIM + n0 + tid];
    __syncthreads();

    size_t eo = (size_t)e * HDIM * HDIM;
    const bf16* w2h = g_w2hi + eo;
    const bf16* w2v = g_w2v  + eo;

    int rr   = tid >> 3;
    int cseg = (tid & 7) * 8;
    uint32_t asw = swz((uint32_t)((rr << 7) | ((tid & 7) << 4)));
    size_t arow[4];
    #pragma unroll
    for (int it = 0; it < 4; it++) {
        int row  = rr + 32 * it;
        int ar   = (base + row < cnt) ? (off + base + row) : off;
        arow[it] = (size_t)ar * HDIM;
    }
    size_t brow = (size_t)(n0 + rr) * HDIM;

    auto load_chunk = [&](int c) {
        int st  = c % B_NST;
        int kk0 = (c & 15) << 6;
        const bf16* As = (c < 16) ? g_ihi : g_iu;
        const bf16* Bs = (c < 16) ? w2h : w2v;
        uint32_t sa = sb + 2048 + st * B_STG;
        #pragma unroll
        for (int it = 0; it < 4; it++)
            cp16(sa + asw + it * 4096, As + arow[it] + kk0 + cseg);
        #pragma unroll
        for (int it = 0; it < 2; it++)
            cp16(sa + 16384 + asw + it * 4096,
                 Bs + brow + (size_t)(it * 32) * HDIM + kk0 + cseg);
        CP_COMMIT();
    };

    int arow_lm = (lane & 15);
    int ahalf   = (lane >> 4);
    int nrow_lm = ((lane >> 4) << 3) + (lane & 7);
    int bhalf   = (lane >> 3) & 1;

    float acc[2][4][4];
    #pragma unroll
    for (int i = 0; i < 2; i++)
        #pragma unroll
        for (int j = 0; j < 4; j++)
            #pragma unroll
            for (int q = 0; q < 4; q++) acc[i][j][q] = 0.f;

    load_chunk(0); load_chunk(1);

    for (int c = 0; c < NCH; c++) {
        CP_WAIT(1);
        __syncthreads();
        if (c + 2 < NCH) load_chunk(c + 2);
        else CP_COMMIT();
        if (c == 16) {
            #pragma unroll
            for (int i = 0; i < 2; i++)
                #pragma unroll
                for (int j = 0; j < 4; j++)
                    #pragma unroll
                    for (int q = 0; q < 4; q++) acc[i][j][q] *= OMEPS;
        }
        uint32_t sa = sb + 2048 + (c % B_NST) * B_STG;
        #pragma unroll
        for (int kk = 0; kk < 4; kk++) {
            uint32_t a[2][4];
            #pragma unroll
            for (int i = 0; i < 2; i++) {
                int row = m32 + i * 16 + arow_lm;
                uint32_t o = (uint32_t)(row * 128 + (kk * 2 + ahalf) * 16);
                LDSM4(a[i][0], a[i][1], a[i][2], a[i][3], sa + swz(o));
            }
            #pragma unroll
            for (int jj = 0; jj < 2; jj++) {
                int nrow = n32 + jj * 16 + nrow_lm;
                uint32_t sw = swz((uint32_t)(nrow * 128 + (kk * 2 + bhalf) * 16));
                uint32_t b0, b1r, b2r, b3r;
                LDSM4(b0, b1r, b2r, b3r, sa + 16384 + sw);
                #pragma unroll
                for (int i = 0; i < 2; i++) {
                    MMA16816(acc[i][2*jj],   a[i][0], a[i][1], a[i][2], a[i][3], b0, b1r);
                    MMA16816(acc[i][2*jj+1], a[i][0], a[i][1], a[i][2], a[i][3], b2r, b3r);
                }
            }
        }
    }

    int mrows = cnt - base; if (mrows > BM) mrows = BM;
    #pragma unroll
    for (int i = 0; i < 2; i++) {
        int r0 = m32 + i * 16 + (lane >> 2);
        int r1 = r0 + 8;
        float* d0 = out + (size_t)stok[r0] * HDIM + n0;
        float* d1 = out + (size_t)stok[r1 < BM ? r1 : 0] * HDIM + n0;
        #pragma unroll
        for (int j = 0; j < 4; j++) {
            int n = n32 + j * 8 + (lane & 3) * 2;
            float ba = sb2[n], bb = sb2[n + 1];
            if (r0 < mrows) {
                float2 o0 = make_float2(acc[i][j][0] + ba, acc[i][j][1] + bb);
                *(float2*)(d0 + n) = o0;
            }
            if (r1 < mrows) {
                float2 o1 = make_float2(acc[i][j][2] + ba, acc[i][j][3] + bb);
                *(float2*)(d1 + n) = o1;
            }
        }
    }
}

// ============================================================
extern "C" void kernel_launch(void* const* d_in, const int* in_sizes, int n_in,
                              void* d_out, int out_size) {
    (void)in_sizes; (void)n_in; (void)out_size;
    const float* x  = (const float*)d_in[0];
    const float* W1 = (const float*)d_in[1];
    const float* b1 = (const float*)d_in[2];
    const float* W2 = (const float*)d_in[3];
    const float* b2 = (const float*)d_in[4];
    const float* W3 = (const float*)d_in[5];
    const float* b3 = (const float*)d_in[6];
    const float* Wg = (const float*)d_in[7];
    const float* bg = (const float*)d_in[8];
    const float* gu = (const float*)d_in[9];
    float* out = (float*)d_out;

    cudaFuncSetAttribute(passA_mma, cudaFuncAttributeMaxDynamicSharedMemorySize, A_SMEM);
    cudaFuncSetAttribute(passB_mma, cudaFuncAttributeMaxDynamicSharedMemorySize, B_SMEM);

    zero_kernel<<<1, 32>>>();
    gate_kernel<<<N_TOK / 8, 256>>>(x, Wg, bg, gu);
    xsplit_kernel<<<(int)(((size_t)N_TOK * HDIM) / 1024), 256>>>(x);
    {
        dim3 g(32, 32, 9), b(32, 8);
        wsplit_kernel<<<g, b>>>(W1, W3, W2);
    }
    {
        dim3 grid(HDIM / BN, N_TOK / BM, NEXP);
        passA_mma<<<grid, 256, A_SMEM>>>(b1, b3);
        passB_mma<<<grid, 256, B_SMEM>>>(b2, out);
    }
}

// round 13
// speedup vs baseline: 1.7470x; 1.0729x over previous
#include <cuda_runtime.h>
#include <cuda_bf16.h>
#include <math.h>
#include <stdint.h>

#define N_TOK 65536
#define HDIM  1024
#define NEXP  3
#define NCH   32          // 16 chunks P = hi.hi  +  16 chunks Q = u.v
#define BM    128
#define BN    64
#define BMB   256         // pass B M-tile
#define EPS   0.03125f    // 2^-5
#define OMEPS 0.96875f    // 1 - 2^-5

typedef __nv_bfloat16 bf16;

// ------------------- scratch (allocation-free) -------------------
__device__ int  g_cursor[NEXP];
__device__ int  g_idx[NEXP * N_TOK];
__device__ bf16 g_xhi[(size_t)N_TOK * HDIM];
__device__ bf16 g_xu [(size_t)N_TOK * HDIM];   // bf16(x_lo + EPS*x_hi)
__device__ bf16 g_ihi[(size_t)N_TOK * HDIM];
__device__ bf16 g_iu [(size_t)N_TOK * HDIM];
__device__ bf16 g_w1hi[(size_t)NEXP * HDIM * HDIM];
__device__ bf16 g_w1v [(size_t)NEXP * HDIM * HDIM];  // bf16(w_hi + w_lo/EPS)
__device__ bf16 g_w3hi[(size_t)NEXP * HDIM * HDIM];
__device__ bf16 g_w3v [(size_t)NEXP * HDIM * HDIM];
__device__ bf16 g_w2hi[(size_t)NEXP * HDIM * HDIM];
__device__ bf16 g_w2v [(size_t)NEXP * HDIM * HDIM];

// ------------------- helpers -------------------
__device__ __forceinline__ uint32_t s2u(const void* p) {
    return (uint32_t)__cvta_generic_to_shared(p);
}
__device__ __forceinline__ void cp16(uint32_t dst, const void* src) {
    asm volatile("cp.async.cg.shared.global [%0], [%1], 16;" :: "r"(dst), "l"(src));
}
#define CP_COMMIT() asm volatile("cp.async.commit_group;" ::: "memory")
#define CP_WAIT(n)  asm volatile("cp.async.wait_group %0;" :: "n"(n) : "memory")

#define LDSM4(r0,r1,r2,r3,addr) \
    asm volatile("ldmatrix.sync.aligned.m8n8.x4.shared.b16 {%0,%1,%2,%3}, [%4];" \
        : "=r"(r0), "=r"(r1), "=r"(r2), "=r"(r3) : "r"(addr))

#define MMA16816(d, a0,a1,a2,a3, b0,b1) \
    asm volatile("mma.sync.aligned.m16n8k16.row.col.f32.bf16.bf16.f32 " \
        "{%0,%1,%2,%3}, {%4,%5,%6,%7}, {%8,%9}, {%0,%1,%2,%3};" \
        : "+f"((d)[0]), "+f"((d)[1]), "+f"((d)[2]), "+f"((d)[3]) \
        : "r"(a0), "r"(a1), "r"(a2), "r"(a3), "r"(b0), "r"(b1))

__device__ __forceinline__ uint32_t swz(uint32_t o) { return o ^ ((o >> 3) & 0x70); }

__device__ __forceinline__ float act_fn(float h1, int e) {
    if (e == 0) return h1 / (1.0f + __expf(-h1));
    if (e == 1) return 0.5f * h1 * (1.0f + erff(h1 * 0.70710678118654752f));
    return fmaxf(h1, 0.0f);
}
__device__ __forceinline__ uint32_t pack_bf2(float a, float b) {
    __nv_bfloat162 t = __halves2bfloat162(__float2bfloat16_rn(a), __float2bfloat16_rn(b));
    return *(uint32_t*)&t;
}

// ============================================================
// Kernel 0: zero per-expert cursors
// ============================================================
__global__ void zero_kernel() {
    if (threadIdx.x < NEXP) g_cursor[threadIdx.x] = 0;
}

// ============================================================
// Kernel 1: gating (one warp per token) + fused x split
// ============================================================
__global__ void gate_kernel(const float* __restrict__ x,
                            const float* __restrict__ Wg,
                            const float* __restrict__ bg,
                            const float* __restrict__ gu) {
    __shared__ float sWg[HDIM * NEXP];
    int tid = threadIdx.x;
    for (int t = tid; t < HDIM * NEXP; t += blockDim.x) sWg[t] = Wg[t];
    __syncthreads();

    int warp = tid >> 5, lane = tid & 31;
    int n = blockIdx.x * 8 + warp;
    const float* xr = x + (size_t)n * HDIM;
    size_t xo = (size_t)n * HDIM + lane;

    float a0 = 0.f, a1 = 0.f, a2 = 0.f;
    #pragma unroll 8
    for (int j = 0; j < HDIM; j += 32) {
        float xi = xr[j + lane];
        // fused split: hi = bf16(x), u = bf16((x-hi) + EPS*hi)
        bf16 h = __float2bfloat16_rn(xi);
        float hf = __bfloat162float(h);
        g_xhi[xo + j] = h;
        g_xu [xo + j] = __float2bfloat16_rn((xi - hf) + EPS * hf);
        const float* w = &sWg[(j + lane) * 3];
        a0 += xi * w[0];
        a1 += xi * w[1];
        a2 += xi * w[2];
    }
    #pragma unroll
    for (int off = 16; off > 0; off >>= 1) {
        a0 += __shfl_down_sync(0xffffffffu, a0, off);
        a1 += __shfl_down_sync(0xffffffffu, a1, off);
        a2 += __shfl_down_sync(0xffffffffu, a2, off);
    }
    if (lane == 0) {
        float s[3];
        s[0] = a0 + bg[0];
        s[1] = a1 + bg[1];
        s[2] = a2 + bg[2];
        #pragma unroll
        for (int e = 0; e < 3; e++) {
            float u = gu[(size_t)n * 3 + e];
            u = fminf(fmaxf(u, 1e-6f), 1.0f - 1e-6f);
            s[e] += -logf(-logf(u));
        }
        int best = 0;
        if (s[1] > s[best]) best = 1;
        if (s[2] > s[best]) best = 2;
        int pos = atomicAdd(&g_cursor[best], 1);
        g_idx[best * N_TOK + pos] = n;
    }
}

// ============================================================
// Kernel 3: transpose + split weights (K-major):
//   hi = bf16(w) ; v = bf16(hi + (w - hi)/EPS)
// ============================================================
__global__ void wsplit_kernel(const float* __restrict__ W1,
                              const float* __restrict__ W3,
                              const float* __restrict__ W2) {
    __shared__ float t[32][33];
    int z = blockIdx.z;
    int mat = z / 3, e = z % 3;
    const float* src;
    bf16 *dh, *dv;
    if (mat == 0)      { src = W1; dh = g_w1hi; dv = g_w1v; }
    else if (mat == 1) { src = W3; dh = g_w3hi; dv = g_w3v; }
    else               { src = W2; dh = g_w2hi; dv = g_w2v; }
    size_t eo = (size_t)e * HDIM * HDIM;
    src += eo; dh += eo; dv += eo;

    int bx = blockIdx.x * 32, by = blockIdx.y * 32;
    int tx = threadIdx.x;
    for (int i = threadIdx.y; i < 32; i += 8)
        t[i][tx] = src[(size_t)(by + i) * HDIM + bx + tx];
    __syncthreads();
    for (int i = threadIdx.y; i < 32; i += 8) {
        float w = t[tx][i];                              // = W[by+tx][bx+i]
        size_t di = (size_t)(bx + i) * HDIM + by + tx;   // Wt[h][d]
        bf16 h = __float2bfloat16_rn(w);
        float hf = __bfloat162float(h);
        dh[di] = h;
        dv[di] = __float2bfloat16_rn(hf + (w - hf) * (1.0f / EPS));
    }
}

// ============================================================
// Kernel 4: pass A — dual GEMM (h1, h3) + activation
//   result = (1-EPS)*P + Q. Tile 128x64, 256 thr, 4m x 2n,
//   3-stage cp.async, 2 CTAs/SM. grid (16, 512, 3)
//   (unchanged from R11 winner)
// ============================================================
#define A_STG  32768
#define A_NST  3
#define A_SMEM (2048 + A_NST * A_STG)

__global__ __launch_bounds__(256, 2)
void passA_mma(const float* __restrict__ b1, const float* __restrict__ b3) {
    int e    = blockIdx.z;
    int cnt  = g_cursor[e];
    int base = blockIdx.y * BM;
    if (base >= cnt) return;
    int n0  = blockIdx.x * BN;
    int tid = threadIdx.x, wid = tid >> 5, lane = tid & 31;
    int m32 = (wid & 3) * 32;
    int n32 = (wid >> 2) * 32;

    extern __shared__ char smem[];
    uint32_t sb = s2u(smem);

    int off = 0;
    for (int i = 0; i < e; i++) off += g_cursor[i];

    int*   srow = (int*)(smem);
    float* sb1  = (float*)(smem + 512);
    float* sb3  = (float*)(smem + 768);
    if (tid < BM) {
        int p = base + tid;
        srow[tid] = (p < cnt) ? g_idx[e * N_TOK + p] : g_idx[e * N_TOK];
    }
    if (tid < BN) {
        sb1[tid] = b1[e * HDIM + n0 + tid];
        sb3[tid] = b3[e * HDIM + n0 + tid];
    }
    __syncthreads();

    size_t eo = (size_t)e * HDIM * HDIM;
    const bf16* w1h = g_w1hi + eo;
    const bf16* w1v = g_w1v  + eo;
    const bf16* w3h = g_w3hi + eo;
    const bf16* w3v = g_w3v  + eo;

    int rr   = tid >> 3;
    int cseg = (tid & 7) * 8;
    uint32_t asw = swz((uint32_t)((rr << 7) | ((tid & 7) << 4)));
    size_t arow[4];
    #pragma unroll
    for (int it = 0; it < 4; it++)
        arow[it] = (size_t)srow[rr + 32 * it] * HDIM;
    size_t brow = (size_t)(n0 + rr) * HDIM;

    auto load_chunk = [&](int c) {
        int st  = c % A_NST;
        int kk0 = (c & 15) << 6;
        const bf16* As  = (c < 16) ? g_xhi : g_xu;
        const bf16* B1s = (c < 16) ? w1h : w1v;
        const bf16* B3s = (c < 16) ? w3h : w3v;
        uint32_t sa = sb + 2048 + st * A_STG;
        #pragma unroll
        for (int it = 0; it < 4; it++)
            cp16(sa + asw + it * 4096, As + arow[it] + kk0 + cseg);
        #pragma unroll
        for (int it = 0; it < 2; it++) {
            size_t g = brow + (size_t)(it * 32) * HDIM + kk0 + cseg;
            cp16(sa + 16384 + asw + it * 4096, B1s + g);
            cp16(sa + 24576 + asw + it * 4096, B3s + g);
        }
        CP_COMMIT();
    };

    int arow_lm = (lane & 15);
    int ahalf   = (lane >> 4);
    int nrow_lm = ((lane >> 4) << 3) + (lane & 7);
    int bhalf   = (lane >> 3) & 1;

    float acc1[2][4][4];
    float acc3[2][4][4];
    #pragma unroll
    for (int i = 0; i < 2; i++)
        #pragma unroll
        for (int j = 0; j < 4; j++)
            #pragma unroll
            for (int q = 0; q < 4; q++) { acc1[i][j][q] = 0.f; acc3[i][j][q] = 0.f; }

    load_chunk(0); load_chunk(1);

    for (int c = 0; c < NCH; c++) {
        CP_WAIT(1);
        __syncthreads();
        if (c + 2 < NCH) load_chunk(c + 2);
        else CP_COMMIT();
        if (c == 16) {
            #pragma unroll
            for (int i = 0; i < 2; i++)
                #pragma unroll
                for (int j = 0; j < 4; j++)
                    #pragma unroll
                    for (int q = 0; q < 4; q++) {
                        acc1[i][j][q] *= OMEPS;
                        acc3[i][j][q] *= OMEPS;
                    }
        }
        uint32_t sa = sb + 2048 + (c % A_NST) * A_STG;
        #pragma unroll
        for (int kk = 0; kk < 4; kk++) {
            uint32_t a[2][4];
            #pragma unroll
            for (int i = 0; i < 2; i++) {
                int row = m32 + i * 16 + arow_lm;
                uint32_t o = (uint32_t)(row * 128 + (kk * 2 + ahalf) * 16);
                LDSM4(a[i][0], a[i][1], a[i][2], a[i][3], sa + swz(o));
            }
            #pragma unroll
            for (int jj = 0; jj < 2; jj++) {
                int nrow = n32 + jj * 16 + nrow_lm;
                uint32_t sw = swz((uint32_t)(nrow * 128 + (kk * 2 + bhalf) * 16));
                uint32_t b0, b1r, b2r, b3r, c0, c1r, c2r, c3r;
                LDSM4(b0, b1r, b2r, b3r, sa + 16384 + sw);
                LDSM4(c0, c1r, c2r, c3r, sa + 24576 + sw);
                #pragma unroll
                for (int i = 0; i < 2; i++) {
                    MMA16816(acc1[i][2*jj],   a[i][0], a[i][1], a[i][2], a[i][3], b0, b1r);
                    MMA16816(acc1[i][2*jj+1], a[i][0], a[i][1], a[i][2], a[i][3], b2r, b3r);
                    MMA16816(acc3[i][2*jj],   a[i][0], a[i][1], a[i][2], a[i][3], c0, c1r);
                    MMA16816(acc3[i][2*jj+1], a[i][0], a[i][1], a[i][2], a[i][3], c2r, c3r);
                }
            }
        }
    }

    int mrows = cnt - base; if (mrows > BM) mrows = BM;
    #pragma unroll
    for (int i = 0; i < 2; i++) {
        int r0 = m32 + i * 16 + (lane >> 2);
        int r1 = r0 + 8;
        size_t g0 = (size_t)(off + base + r0) * HDIM;
        size_t g1 = (size_t)(off + base + r1) * HDIM;
        #pragma unroll
        for (int j = 0; j < 4; j++) {
            int n = n32 + j * 8 + (lane & 3) * 2;
            float bb1a = sb1[n], bb1b = sb1[n + 1];
            float bb3a = sb3[n], bb3b = sb3[n + 1];
            if (r0 < mrows) {
                float v0 = act_fn(acc1[i][j][0] + bb1a, e) * (acc3[i][j][0] + bb3a);
                float v1 = act_fn(acc1[i][j][1] + bb1b, e) * (acc3[i][j][1] + bb3b);
                bf16 h0 = __float2bfloat16_rn(v0), h1 = __float2bfloat16_rn(v1);
                float f0 = __bfloat162float(h0), f1 = __bfloat162float(h1);
                *(uint32_t*)(g_ihi + g0 + n0 + n) = pack_bf2(v0, v1);
                *(uint32_t*)(g_iu  + g0 + n0 + n) =
                    pack_bf2((v0 - f0) + EPS * f0, (v1 - f1) + EPS * f1);
            }
            if (r1 < mrows) {
                float v2 = act_fn(acc1[i][j][2] + bb1a, e) * (acc3[i][j][2] + bb3a);
                float v3 = act_fn(acc1[i][j][3] + bb1b, e) * (acc3[i][j][3] + bb3b);
                bf16 h2 = __float2bfloat16_rn(v2), h3 = __float2bfloat16_rn(v3);
                float f2 = __bfloat162float(h2), f3 = __bfloat162float(h3);
                *(uint32_t*)(g_ihi + g1 + n0 + n) = pack_bf2(v2, v3);
                *(uint32_t*)(g_iu  + g1 + n0 + n) =
                    pack_bf2((v2 - f2) + EPS * f2, (v3 - f3) + EPS * f3);
            }
        }
    }
}

// ============================================================
// Kernel 5: pass B — GEMM inner@W2 + b2, scatter
//   Tile 256x64, 256 thr, 8 warps 4m x 2n (warp tile 64x32),
//   2-stage cp.async, 2 CTAs/SM. grid (16, 256, 3)
// ============================================================
#define B_STG  40960
#define B_SMEM (2048 + 2 * B_STG)

__global__ __launch_bounds__(256, 2)
void passB_mma(const float* __restrict__ b2, float* __restrict__ out) {
    int e    = blockIdx.z;
    int cnt  = g_cursor[e];
    int base = blockIdx.y * BMB;
    if (base >= cnt) return;
    int n0  = blockIdx.x * BN;
    int tid = threadIdx.x, wid = tid >> 5, lane = tid & 31;
    int m64 = (wid & 3) * 64;
    int n32 = (wid >> 2) * 32;

    extern __shared__ char smem[];
    uint32_t sb = s2u(smem);

    int off = 0;
    for (int i = 0; i < e; i++) off += g_cursor[i];

    int*   stok = (int*)(smem);              // 256 ints = 1024 B
    float* sb2  = (float*)(smem + 1024);     // 64 floats
    {
        int p = base + tid;
        stok[tid] = (p < cnt) ? g_idx[e * N_TOK + p] : 0;
    }
    if (tid < BN) sb2[tid] = b2[e * HDIM + n0 + tid];
    __syncthreads();

    size_t eo = (size_t)e * HDIM * HDIM;
    const bf16* w2h = g_w2hi + eo;
    const bf16* w2v = g_w2v  + eo;

    int rr   = tid >> 3;                  // 0..31
    int cseg = (tid & 7) * 8;
    uint32_t asw = swz((uint32_t)((rr << 7) | ((tid & 7) << 4)));
    size_t arow[8];
    #pragma unroll
    for (int it = 0; it < 8; it++) {
        int row  = rr + 32 * it;
        int ar   = (base + row < cnt) ? (off + base + row) : off;
        arow[it] = (size_t)ar * HDIM;
    }
    size_t brow = (size_t)(n0 + rr) * HDIM;

    auto load_chunk = [&](int c) {
        int st  = c & 1;
        int kk0 = (c & 15) << 6;
        const bf16* As = (c < 16) ? g_ihi : g_iu;
        const bf16* Bs = (c < 16) ? w2h : w2v;
        uint32_t sa = sb + 2048 + st * B_STG;
        #pragma unroll
        for (int it = 0; it < 8; it++)
            cp16(sa + asw + it * 4096, As + arow[it] + kk0 + cseg);
        #pragma unroll
        for (int it = 0; it < 2; it++)
            cp16(sa + 32768 + asw + it * 4096,
                 Bs + brow + (size_t)(it * 32) * HDIM + kk0 + cseg);
        CP_COMMIT();
    };

    int arow_lm = (lane & 15);
    int ahalf   = (lane >> 4);
    int nrow_lm = ((lane >> 4) << 3) + (lane & 7);
    int bhalf   = (lane >> 3) & 1;

    float acc[4][4][4];
    #pragma unroll
    for (int i = 0; i < 4; i++)
        #pragma unroll
        for (int j = 0; j < 4; j++)
            #pragma unroll
            for (int q = 0; q < 4; q++) acc[i][j][q] = 0.f;

    load_chunk(0);

    for (int c = 0; c < NCH; c++) {
        CP_WAIT(0);
        __syncthreads();
        if (c + 1 < NCH) load_chunk(c + 1);
        if (c == 16) {
            #pragma unroll
            for (int i = 0; i < 4; i++)
                #pragma unroll
                for (int j = 0; j < 4; j++)
                    #pragma unroll
                    for (int q = 0; q < 4; q++) acc[i][j][q] *= OMEPS;
        }
        uint32_t sa = sb + 2048 + (c & 1) * B_STG;
        #pragma unroll
        for (int kk = 0; kk < 4; kk++) {
            uint32_t a[4][4];
            #pragma unroll
            for (int i = 0; i < 4; i++) {
                int row = m64 + i * 16 + arow_lm;
                uint32_t o = (uint32_t)(row * 128 + (kk * 2 + ahalf) * 16);
                LDSM4(a[i][0], a[i][1], a[i][2], a[i][3], sa + swz(o));
            }
            #pragma unroll
            for (int jj = 0; jj < 2; jj++) {
                int nrow = n32 + jj * 16 + nrow_lm;
                uint32_t sw = swz((uint32_t)(nrow * 128 + (kk * 2 + bhalf) * 16));
                uint32_t b0, b1r, b2r, b3r;
                LDSM4(b0, b1r, b2r, b3r, sa + 32768 + sw);
                #pragma unroll
                for (int i = 0; i < 4; i++) {
                    MMA16816(acc[i][2*jj],   a[i][0], a[i][1], a[i][2], a[i][3], b0, b1r);
                    MMA16816(acc[i][2*jj+1], a[i][0], a[i][1], a[i][2], a[i][3], b2r, b3r);
                }
            }
        }
    }

    int mrows = cnt - base; if (mrows > BMB) mrows = BMB;
    #pragma unroll
    for (int i = 0; i < 4; i++) {
        int r0 = m64 + i * 16 + (lane >> 2);
        int r1 = r0 + 8;
        float* d0 = out + (size_t)stok[r0] * HDIM + n0;
        float* d1 = out + (size_t)stok[r1] * HDIM + n0;
        #pragma unroll
        for (int j = 0; j < 4; j++) {
            int n = n32 + j * 8 + (lane & 3) * 2;
            float ba = sb2[n], bb = sb2[n + 1];
            if (r0 < mrows) {
                float2 o0 = make_float2(acc[i][j][0] + ba, acc[i][j][1] + bb);
                *(float2*)(d0 + n) = o0;
            }
            if (r1 < mrows) {
                float2 o1 = make_float2(acc[i][j][2] + ba, acc[i][j][3] + bb);
                *(float2*)(d1 + n) = o1;
            }
        }
    }
}

// ============================================================
extern "C" void kernel_launch(void* const* d_in, const int* in_sizes, int n_in,
                              void* d_out, int out_size) {
    (void)in_sizes; (void)n_in; (void)out_size;
    const float* x  = (const float*)d_in[0];
    const float* W1 = (const float*)d_in[1];
    const float* b1 = (const float*)d_in[2];
    const float* W2 = (const float*)d_in[3];
    const float* b2 = (const float*)d_in[4];
    const float* W3 = (const float*)d_in[5];
    const float* b3 = (const float*)d_in[6];
    const float* Wg = (const float*)d_in[7];
    const float* bg = (const float*)d_in[8];
    const float* gu = (const float*)d_in[9];
    float* out = (float*)d_out;

    cudaFuncSetAttribute(passA_mma, cudaFuncAttributeMaxDynamicSharedMemorySize, A_SMEM);
    cudaFuncSetAttribute(passB_mma, cudaFuncAttributeMaxDynamicSharedMemorySize, B_SMEM);

    zero_kernel<<<1, 32>>>();
    gate_kernel<<<N_TOK / 8, 256>>>(x, Wg, bg, gu);
    {
        dim3 g(32, 32, 9), b(32, 8);
        wsplit_kernel<<<g, b>>>(W1, W3, W2);
    }
    {
        dim3 gridA(HDIM / BN, N_TOK / BM, NEXP);
        passA_mma<<<gridA, 256, A_SMEM>>>(b1, b3);
        dim3 gridB(HDIM / BN, N_TOK / BMB, NEXP);
        passB_mma<<<gridB, 256, B_SMEM>>>(b2, out);
    }
}